// round 3
// baseline (speedup 1.0000x reference)
#include <cuda_runtime.h>

// NATSearch: 2D neighborhood attention (NATTEN-style), fp32.
// N=4 images, H=W=64, C=64, HEADS=2, dh=32, K=7.
// qkv GEMM (8x8 register microkernel) -> dual-head neighborhood attention
// -> proj GEMM (4x4 register microkernel).

#define NIMG   4
#define HW     64
#define CCH    64
#define NHEADS 2
#define DHEAD  32
#define KWIN   7
#define NPIX   (NIMG * HW * HW)   // 16384
#define QKVD   192
#define NBDIM  14                 // neighborhood tile extent per 8x8 query tile
#define NNB    (NBDIM * NBDIM)    // 196
#define PITCH  68                 // smem row pitch (floats): 64 data + 4 pad
#define QSCALE 0.17677669529663687f  // 32^-0.5

__device__ float g_qkv[NPIX * QKVD];        // [pix][192]: q(64) k(64) v(64)
__device__ float g_att[CCH * NPIX];         // c-major: [c][pix] (for proj transpose-free load)

// ---------------------------------------------------------------------------
// Kernel 1: qkv = x @ w_qkv + b_qkv. Block tile: 64 px x 192 cols, 192 threads,
// each thread computes an 8x8 register tile. x staged transposed in smem.
// ---------------------------------------------------------------------------
__global__ void __launch_bounds__(192) qkv_kernel(const float* __restrict__ vid,
                                                  const float* __restrict__ w_qkv,
                                                  const float* __restrict__ b_qkv) {
    __shared__ float xs[64][64];   // [c][px]
    const int tid  = threadIdx.x;
    const int pix0 = blockIdx.x * 64;            // one full image row (x fixed)
    const int n  = pix0 >> 12;
    const int xr = (pix0 >> 6) & 63;
    const float* vbase = vid + n * 262144 + xr * 64;

    for (int i = tid; i < 1024; i += 192) {      // 64 c x 16 quads
        const int c = i >> 4, qq = i & 15;
        *(float4*)&xs[c][qq * 4] = *(const float4*)(vbase + c * 4096 + qq * 4);
    }
    __syncthreads();

    const int pg = tid / 24, jg = tid % 24;      // 8 px-groups x 24 j-groups
    const int px0 = pg * 8, j0 = jg * 8;

    float acc[8][8];
#pragma unroll
    for (int p = 0; p < 8; p++)
#pragma unroll
        for (int j = 0; j < 8; j++) acc[p][j] = 0.f;

#pragma unroll 4
    for (int c = 0; c < 64; c++) {
        const float4 xa = *(const float4*)&xs[c][px0];
        const float4 xb = *(const float4*)&xs[c][px0 + 4];
        const float4 wa = *(const float4*)(w_qkv + c * QKVD + j0);
        const float4 wb = *(const float4*)(w_qkv + c * QKVD + j0 + 4);
        float xv[8] = {xa.x, xa.y, xa.z, xa.w, xb.x, xb.y, xb.z, xb.w};
        float wv[8] = {wa.x, wa.y, wa.z, wa.w, wb.x, wb.y, wb.z, wb.w};
#pragma unroll
        for (int p = 0; p < 8; p++)
#pragma unroll
            for (int j = 0; j < 8; j++) acc[p][j] += xv[p] * wv[j];
    }

    const float4 ba = *(const float4*)(b_qkv + j0);
    const float4 bb = *(const float4*)(b_qkv + j0 + 4);
    const float bv[8] = {ba.x, ba.y, ba.z, ba.w, bb.x, bb.y, bb.z, bb.w};
    const float sc = (j0 < 64) ? QSCALE : 1.0f;  // q block gets dh^-0.5

#pragma unroll
    for (int p = 0; p < 8; p++) {
        float* dst = g_qkv + (size_t)(pix0 + px0 + p) * QKVD + j0;
        float4 r0, r1;
        r0.x = (acc[p][0] + bv[0]) * sc; r0.y = (acc[p][1] + bv[1]) * sc;
        r0.z = (acc[p][2] + bv[2]) * sc; r0.w = (acc[p][3] + bv[3]) * sc;
        r1.x = (acc[p][4] + bv[4]) * sc; r1.y = (acc[p][5] + bv[5]) * sc;
        r1.z = (acc[p][6] + bv[6]) * sc; r1.w = (acc[p][7] + bv[7]) * sc;
        *(float4*)dst = r0;
        *(float4*)(dst + 4) = r1;
    }
}

// ---------------------------------------------------------------------------
// Kernel 2: neighborhood attention. Block = (8x8 query tile, image), 128
// threads = 64 queries x 2 heads. k/v 14x14 neighborhood (full C=64) in smem.
// ---------------------------------------------------------------------------
__global__ void __launch_bounds__(128) attn_kernel(const float* __restrict__ rpb) {
    extern __shared__ float sm[];
    float* ks = sm;                        // [196][PITCH]
    float* vs = sm + NNB * PITCH;          // [196][PITCH]
    float* rs = vs + NNB * PITCH;          // [2][169]

    const int tid  = threadIdx.x;
    const int head = tid >> 6;
    const int qid  = tid & 63;
    const int n    = blockIdx.y;
    const int x0   = (blockIdx.x >> 3) * 8;
    const int y0   = (blockIdx.x & 7) * 8;
    const int rb   = min(max(x0 - 3, 0), 50);
    const int cb   = min(max(y0 - 3, 0), 50);

    // stage k/v: 196 nb pixels x 32 quads (16 k-quads [64,128), 16 v-quads [128,192))
    for (int i = tid; i < NNB * 32; i += 128) {
        const int nb = i >> 5, part = i & 31;
        const int gr = rb + nb / NBDIM, gc = cb + nb % NBDIM;
        const float* src = g_qkv + (size_t)(n * 4096 + gr * 64 + gc) * QKVD;
        if (part < 16) {
            *(float4*)(ks + nb * PITCH + part * 4) = *(const float4*)(src + 64 + part * 4);
        } else {
            *(float4*)(vs + nb * PITCH + (part - 16) * 4) = *(const float4*)(src + 128 + (part - 16) * 4);
        }
    }
    for (int i = tid; i < 2 * 169; i += 128) rs[i] = rpb[i];
    __syncthreads();

    const int qx = qid >> 3, qy = qid & 7;
    const int xx = x0 + qx, yy = y0 + qy;
    const int hb = head * DHEAD;

    float q[32];
    {
        const float* qp = g_qkv + (size_t)(n * 4096 + xx * 64 + yy) * QKVD + hb;
#pragma unroll
        for (int dq = 0; dq < 8; dq++) {
            const float4 t = *(const float4*)(qp + dq * 4);
            q[dq * 4 + 0] = t.x; q[dq * 4 + 1] = t.y;
            q[dq * 4 + 2] = t.z; q[dq * 4 + 3] = t.w;
        }
    }

    const int sx = min(max(xx - 3, 0), 57), sy = min(max(yy - 3, 0), 57);
    const int r0 = sx - rb, c0 = sy - cb;
    const int bh = sx - xx + 6, bw = sy - yy + 6;
    const float* rh = rs + head * 169;

    float lg[49];
#pragma unroll
    for (int a = 0; a < KWIN; a++) {
#pragma unroll
        for (int b = 0; b < KWIN; b++) {
            const float* kp = ks + ((r0 + a) * NBDIM + c0 + b) * PITCH + hb;
            float acc0 = rh[(bh + a) * 13 + bw + b];
            float acc1 = 0.f;
#pragma unroll
            for (int dq = 0; dq < 8; dq++) {
                const float4 k4 = *(const float4*)(kp + dq * 4);
                acc0 += q[dq * 4 + 0] * k4.x + q[dq * 4 + 2] * k4.z;
                acc1 += q[dq * 4 + 1] * k4.y + q[dq * 4 + 3] * k4.w;
            }
            lg[a * KWIN + b] = acc0 + acc1;
        }
    }

    float m = lg[0];
#pragma unroll
    for (int i = 1; i < 49; i++) m = fmaxf(m, lg[i]);
    float s = 0.f;
#pragma unroll
    for (int i = 0; i < 49; i++) { const float e = __expf(lg[i] - m); lg[i] = e; s += e; }
    const float inv = 1.0f / s;

    float o[32];
#pragma unroll
    for (int d = 0; d < 32; d++) o[d] = 0.f;
#pragma unroll
    for (int a = 0; a < KWIN; a++) {
#pragma unroll
        for (int b = 0; b < KWIN; b++) {
            const float w = lg[a * KWIN + b];
            const float* vp = vs + ((r0 + a) * NBDIM + c0 + b) * PITCH + hb;
#pragma unroll
            for (int dq = 0; dq < 8; dq++) {
                const float4 v4 = *(const float4*)(vp + dq * 4);
                o[dq * 4 + 0] += w * v4.x; o[dq * 4 + 1] += w * v4.y;
                o[dq * 4 + 2] += w * v4.z; o[dq * 4 + 3] += w * v4.w;
            }
        }
    }

    // store c-major: g_att[c][pix] (coalesced across qy within the warp)
    const int pix = n * 4096 + xx * 64 + yy;
#pragma unroll
    for (int d = 0; d < 32; d++) g_att[(size_t)(hb + d) * NPIX + pix] = o[d] * inv;
}

// ---------------------------------------------------------------------------
// Kernel 3: out = attn @ w_proj + b_proj. Block tile: 64 px x 64 cols,
// 256 threads, 4x4 register tile each. g_att is c-major -> direct float4 fill.
// ---------------------------------------------------------------------------
__global__ void __launch_bounds__(256) proj_kernel(const float* __restrict__ w_proj,
                                                   const float* __restrict__ b_proj,
                                                   float* __restrict__ out, int out_size) {
    __shared__ float xs[64][64];   // [c][px]
    const int tid  = threadIdx.x;
    const int pix0 = blockIdx.x * 64;

    for (int i = tid; i < 1024; i += 256) {      // 64 c x 16 quads
        const int c = i >> 4, qq = i & 15;
        *(float4*)&xs[c][qq * 4] = *(const float4*)(g_att + (size_t)c * NPIX + pix0 + qq * 4);
    }
    __syncthreads();

    const int pg = tid >> 4, jg = tid & 15;      // 16 px-groups x 16 j-groups
    const int px0 = pg * 4, j0 = jg * 4;

    float acc[4][4];
#pragma unroll
    for (int p = 0; p < 4; p++)
#pragma unroll
        for (int j = 0; j < 4; j++) acc[p][j] = 0.f;

#pragma unroll 8
    for (int c = 0; c < 64; c++) {
        const float4 xa = *(const float4*)&xs[c][px0];
        const float4 wa = *(const float4*)(w_proj + c * 64 + j0);
        const float xv[4] = {xa.x, xa.y, xa.z, xa.w};
        const float wv[4] = {wa.x, wa.y, wa.z, wa.w};
#pragma unroll
        for (int p = 0; p < 4; p++)
#pragma unroll
            for (int j = 0; j < 4; j++) acc[p][j] += xv[p] * wv[j];
    }

    const float4 b4 = *(const float4*)(b_proj + j0);
#pragma unroll
    for (int p = 0; p < 4; p++) {
        float4 r;
        r.x = acc[p][0] + b4.x; r.y = acc[p][1] + b4.y;
        r.z = acc[p][2] + b4.z; r.w = acc[p][3] + b4.w;
        *(float4*)(out + (size_t)(pix0 + px0 + p) * 64 + j0) = r;
    }

    // zero the inds tail (and any extra output elements)
    if (blockIdx.x == 0) {
        for (int i = NPIX * CCH + tid; i < out_size; i += 256) out[i] = 0.0f;
    }
}

// ---------------------------------------------------------------------------
extern "C" void kernel_launch(void* const* d_in, const int* in_sizes, int n_in,
                              void* d_out, int out_size) {
    const float* vid    = (const float*)d_in[0];
    const float* w_qkv  = (const float*)d_in[4];
    const float* b_qkv  = (const float*)d_in[5];
    const float* rpb    = (const float*)d_in[6];
    const float* w_proj = (const float*)d_in[7];
    const float* b_proj = (const float*)d_in[8];
    float* out = (float*)d_out;

    qkv_kernel<<<NPIX / 64, 192>>>(vid, w_qkv, b_qkv);

    const int smem = (2 * NNB * PITCH + 2 * 169) * (int)sizeof(float);  // ~108 KB
    cudaFuncSetAttribute(attn_kernel, cudaFuncAttributeMaxDynamicSharedMemorySize, smem);
    attn_kernel<<<dim3(64, NIMG), 128, smem>>>(rpb);

    proj_kernel<<<NPIX / 64, 256>>>(w_proj, b_proj, out, out_size);
}

// round 4
// speedup vs baseline: 1.0461x; 1.0461x over previous
#include <cuda_runtime.h>

// NATSearch: 2D neighborhood attention (NATTEN-style), fp32.
// N=4 images, H=W=64, C=64, HEADS=2, dh=32, K=7.
// qkv GEMM (8x8 microkernel, BOTH operands staged in smem)
// -> dual-head neighborhood attention -> proj GEMM (4x4 microkernel).

#define NIMG   4
#define HW     64
#define CCH    64
#define NHEADS 2
#define DHEAD  32
#define KWIN   7
#define NPIX   (NIMG * HW * HW)   // 16384
#define QKVD   192
#define NBDIM  14                 // neighborhood tile extent per 8x8 query tile
#define NNB    (NBDIM * NBDIM)    // 196
#define PITCH  68                 // smem row pitch (floats): 64 data + 4 pad
#define QSCALE 0.17677669529663687f  // 32^-0.5

__device__ float g_qkv[NPIX * QKVD];        // [pix][192]: q(64) k(64) v(64)
__device__ float g_att[CCH * NPIX];         // c-major: [c][pix]

// ---------------------------------------------------------------------------
// Kernel 1: qkv = x @ w_qkv + b_qkv. Block tile: 64 px x 192 cols, 192 threads,
// 8x8 register tile each. x AND w staged in smem -> smem-only inner loop.
// ---------------------------------------------------------------------------
__global__ void __launch_bounds__(192) qkv_kernel(const float* __restrict__ vid,
                                                  const float* __restrict__ w_qkv,
                                                  const float* __restrict__ b_qkv) {
    extern __shared__ float sm[];
    float* xs = sm;            // [64][64]  (c-major: [c][px])
    float* ws = sm + 4096;     // [64][192] (c-major: [c][j])

    const int tid  = threadIdx.x;
    const int pix0 = blockIdx.x * 64;            // one full image row (x fixed)
    const int n  = pix0 >> 12;
    const int xr = (pix0 >> 6) & 63;
    const float* vbase = vid + n * 262144 + xr * 64;

    for (int i = tid; i < 1024; i += 192) {      // 64 c x 16 quads
        const int c = i >> 4, qq = i & 15;
        *(float4*)&xs[c * 64 + qq * 4] = *(const float4*)(vbase + c * 4096 + qq * 4);
    }
    for (int i = tid; i < 3072; i += 192)        // 64x192 floats = 3072 quads
        ((float4*)ws)[i] = ((const float4*)w_qkv)[i];
    __syncthreads();

    const int pg = tid / 24, jg = tid % 24;      // 8 px-groups x 24 j-groups
    const int px0 = pg * 8, j0 = jg * 8;

    float acc[8][8];
#pragma unroll
    for (int p = 0; p < 8; p++)
#pragma unroll
        for (int j = 0; j < 8; j++) acc[p][j] = 0.f;

#pragma unroll 4
    for (int c = 0; c < 64; c++) {
        const float4 xa = *(const float4*)&xs[c * 64 + px0];
        const float4 xb = *(const float4*)&xs[c * 64 + px0 + 4];
        const float4 wa = *(const float4*)&ws[c * QKVD + j0];
        const float4 wb = *(const float4*)&ws[c * QKVD + j0 + 4];
        float xv[8] = {xa.x, xa.y, xa.z, xa.w, xb.x, xb.y, xb.z, xb.w};
        float wv[8] = {wa.x, wa.y, wa.z, wa.w, wb.x, wb.y, wb.z, wb.w};
#pragma unroll
        for (int p = 0; p < 8; p++)
#pragma unroll
            for (int j = 0; j < 8; j++) acc[p][j] += xv[p] * wv[j];
    }

    const float4 ba = *(const float4*)(b_qkv + j0);
    const float4 bb = *(const float4*)(b_qkv + j0 + 4);
    const float bv[8] = {ba.x, ba.y, ba.z, ba.w, bb.x, bb.y, bb.z, bb.w};
    const float sc = (j0 < 64) ? QSCALE : 1.0f;  // q block gets dh^-0.5

#pragma unroll
    for (int p = 0; p < 8; p++) {
        float* dst = g_qkv + (size_t)(pix0 + px0 + p) * QKVD + j0;
        float4 r0, r1;
        r0.x = (acc[p][0] + bv[0]) * sc; r0.y = (acc[p][1] + bv[1]) * sc;
        r0.z = (acc[p][2] + bv[2]) * sc; r0.w = (acc[p][3] + bv[3]) * sc;
        r1.x = (acc[p][4] + bv[4]) * sc; r1.y = (acc[p][5] + bv[5]) * sc;
        r1.z = (acc[p][6] + bv[6]) * sc; r1.w = (acc[p][7] + bv[7]) * sc;
        *(float4*)dst = r0;
        *(float4*)(dst + 4) = r1;
    }
}

// ---------------------------------------------------------------------------
// Kernel 2: neighborhood attention. Block = (8x8 query tile, image), 128
// threads = 64 queries x 2 heads. k/v 14x14 neighborhood (full C=64) in smem.
// ---------------------------------------------------------------------------
__global__ void __launch_bounds__(128) attn_kernel(const float* __restrict__ rpb) {
    extern __shared__ float sm[];
    float* ks = sm;                        // [196][PITCH]
    float* vs = sm + NNB * PITCH;          // [196][PITCH]
    float* rs = vs + NNB * PITCH;          // [2][169]

    const int tid  = threadIdx.x;
    const int head = tid >> 6;
    const int qid  = tid & 63;
    const int n    = blockIdx.y;
    const int x0   = (blockIdx.x >> 3) * 8;
    const int y0   = (blockIdx.x & 7) * 8;
    const int rb   = min(max(x0 - 3, 0), 50);
    const int cb   = min(max(y0 - 3, 0), 50);

    const int qx = qid >> 3, qy = qid & 7;
    const int xx = x0 + qx, yy = y0 + qy;
    const int hb = head * DHEAD;

    // q load first: global fetch overlaps the staging loop below
    float q[32];
    {
        const float* qp = g_qkv + (size_t)(n * 4096 + xx * 64 + yy) * QKVD + hb;
#pragma unroll
        for (int dq = 0; dq < 8; dq++) {
            const float4 t = *(const float4*)(qp + dq * 4);
            q[dq * 4 + 0] = t.x; q[dq * 4 + 1] = t.y;
            q[dq * 4 + 2] = t.z; q[dq * 4 + 3] = t.w;
        }
    }

    // stage k/v: 196 nb pixels x 32 quads (16 k-quads [64,128), 16 v-quads [128,192))
    for (int i = tid; i < NNB * 32; i += 128) {
        const int nb = i >> 5, part = i & 31;
        const int gr = rb + nb / NBDIM, gc = cb + nb % NBDIM;
        const float* src = g_qkv + (size_t)(n * 4096 + gr * 64 + gc) * QKVD;
        if (part < 16) {
            *(float4*)(ks + nb * PITCH + part * 4) = *(const float4*)(src + 64 + part * 4);
        } else {
            *(float4*)(vs + nb * PITCH + (part - 16) * 4) = *(const float4*)(src + 128 + (part - 16) * 4);
        }
    }
    for (int i = tid; i < 2 * 169; i += 128) rs[i] = rpb[i];
    __syncthreads();

    const int sx = min(max(xx - 3, 0), 57), sy = min(max(yy - 3, 0), 57);
    const int r0 = sx - rb, c0 = sy - cb;
    const int bh = sx - xx + 6, bw = sy - yy + 6;
    const float* rh = rs + head * 169;

    float lg[49];
#pragma unroll
    for (int a = 0; a < KWIN; a++) {
#pragma unroll
        for (int b = 0; b < KWIN; b++) {
            const float* kp = ks + ((r0 + a) * NBDIM + c0 + b) * PITCH + hb;
            float a0 = 0.f, a1 = 0.f, a2 = 0.f, a3 = 0.f;   // 4 chains
#pragma unroll
            for (int dq = 0; dq < 8; dq += 2) {
                const float4 k4 = *(const float4*)(kp + dq * 4);
                const float4 k5 = *(const float4*)(kp + dq * 4 + 4);
                a0 += q[dq * 4 + 0] * k4.x + q[dq * 4 + 2] * k4.z;
                a1 += q[dq * 4 + 1] * k4.y + q[dq * 4 + 3] * k4.w;
                a2 += q[dq * 4 + 4] * k5.x + q[dq * 4 + 6] * k5.z;
                a3 += q[dq * 4 + 5] * k5.y + q[dq * 4 + 7] * k5.w;
            }
            lg[a * KWIN + b] = (a0 + a1) + (a2 + a3) + rh[(bh + a) * 13 + bw + b];
        }
    }

    float m = lg[0];
#pragma unroll
    for (int i = 1; i < 49; i++) m = fmaxf(m, lg[i]);
    float s = 0.f;
#pragma unroll
    for (int i = 0; i < 49; i++) { const float e = __expf(lg[i] - m); lg[i] = e; s += e; }
    const float inv = 1.0f / s;

    float o[32];
#pragma unroll
    for (int d = 0; d < 32; d++) o[d] = 0.f;
#pragma unroll
    for (int a = 0; a < KWIN; a++) {
#pragma unroll
        for (int b = 0; b < KWIN; b++) {
            const float w = lg[a * KWIN + b];
            const float* vp = vs + ((r0 + a) * NBDIM + c0 + b) * PITCH + hb;
#pragma unroll
            for (int dq = 0; dq < 8; dq++) {
                const float4 v4 = *(const float4*)(vp + dq * 4);
                o[dq * 4 + 0] += w * v4.x; o[dq * 4 + 1] += w * v4.y;
                o[dq * 4 + 2] += w * v4.z; o[dq * 4 + 3] += w * v4.w;
            }
        }
    }

    // store c-major: g_att[c][pix] (coalesced across qy within the warp)
    const int pix = n * 4096 + xx * 64 + yy;
#pragma unroll
    for (int d = 0; d < 32; d++) g_att[(size_t)(hb + d) * NPIX + pix] = o[d] * inv;
}

// ---------------------------------------------------------------------------
// Kernel 3: out = attn @ w_proj + b_proj. Block tile: 64 px x 64 cols,
// 256 threads, 4x4 register tile each. g_att is c-major -> direct float4 fill.
// ---------------------------------------------------------------------------
__global__ void __launch_bounds__(256) proj_kernel(const float* __restrict__ w_proj,
                                                   const float* __restrict__ b_proj,
                                                   float* __restrict__ out, int out_size) {
    __shared__ float xs[64][64];   // [c][px]
    const int tid  = threadIdx.x;
    const int pix0 = blockIdx.x * 64;

    for (int i = tid; i < 1024; i += 256) {      // 64 c x 16 quads
        const int c = i >> 4, qq = i & 15;
        *(float4*)&xs[c][qq * 4] = *(const float4*)(g_att + (size_t)c * NPIX + pix0 + qq * 4);
    }
    __syncthreads();

    const int pg = tid >> 4, jg = tid & 15;      // 16 px-groups x 16 j-groups
    const int px0 = pg * 4, j0 = jg * 4;

    float acc[4][4];
#pragma unroll
    for (int p = 0; p < 4; p++)
#pragma unroll
        for (int j = 0; j < 4; j++) acc[p][j] = 0.f;

#pragma unroll 8
    for (int c = 0; c < 64; c++) {
        const float4 xa = *(const float4*)&xs[c][px0];
        const float4 wa = *(const float4*)(w_proj + c * 64 + j0);
        const float xv[4] = {xa.x, xa.y, xa.z, xa.w};
        const float wv[4] = {wa.x, wa.y, wa.z, wa.w};
#pragma unroll
        for (int p = 0; p < 4; p++)
#pragma unroll
            for (int j = 0; j < 4; j++) acc[p][j] += xv[p] * wv[j];
    }

    const float4 b4 = *(const float4*)(b_proj + j0);
#pragma unroll
    for (int p = 0; p < 4; p++) {
        float4 r;
        r.x = acc[p][0] + b4.x; r.y = acc[p][1] + b4.y;
        r.z = acc[p][2] + b4.z; r.w = acc[p][3] + b4.w;
        *(float4*)(out + (size_t)(pix0 + px0 + p) * 64 + j0) = r;
    }

    // zero the inds tail (and any extra output elements)
    if (blockIdx.x == 0) {
        for (int i = NPIX * CCH + tid; i < out_size; i += 256) out[i] = 0.0f;
    }
}

// ---------------------------------------------------------------------------
extern "C" void kernel_launch(void* const* d_in, const int* in_sizes, int n_in,
                              void* d_out, int out_size) {
    const float* vid    = (const float*)d_in[0];
    const float* w_qkv  = (const float*)d_in[4];
    const float* b_qkv  = (const float*)d_in[5];
    const float* rpb    = (const float*)d_in[6];
    const float* w_proj = (const float*)d_in[7];
    const float* b_proj = (const float*)d_in[8];
    float* out = (float*)d_out;

    const int qkv_smem = (64 * 64 + 64 * QKVD) * (int)sizeof(float);  // 64 KB
    cudaFuncSetAttribute(qkv_kernel, cudaFuncAttributeMaxDynamicSharedMemorySize, qkv_smem);
    qkv_kernel<<<NPIX / 64, 192, qkv_smem>>>(vid, w_qkv, b_qkv);

    const int attn_smem = (2 * NNB * PITCH + 2 * 169) * (int)sizeof(float);  // ~108 KB
    cudaFuncSetAttribute(attn_kernel, cudaFuncAttributeMaxDynamicSharedMemorySize, attn_smem);
    attn_kernel<<<dim3(64, NIMG), 128, attn_smem>>>(rpb);

    proj_kernel<<<NPIX / 64, 256>>>(w_proj, b_proj, out, out_size);
}

// round 5
// speedup vs baseline: 1.1200x; 1.0706x over previous
#include <cuda_runtime.h>
#include <cuda_fp16.h>

// NATSearch: 2D neighborhood attention (NATTEN-style).
// N=4 images, H=W=64, C=64, HEADS=2, dh=32, K=7.
// qkv GEMM (grid 512, 8x8 microkernel, smem-staged operands; writes q fp32 +
// k/v fp16 planar) -> dual-head neighborhood attention with fp16 k/v in smem
// (fp32 softmax/accum) -> proj GEMM (4x4 microkernel).

#define NIMG   4
#define HW     64
#define CCH    64
#define NHEADS 2
#define DHEAD  32
#define KWIN   7
#define NPIX   (NIMG * HW * HW)   // 16384
#define QKVD   192
#define NBDIM  14                 // neighborhood tile extent per 8x8 query tile
#define NNB    (NBDIM * NBDIM)    // 196
#define KPITCH 72                 // smem row pitch in halfs (64 data + 8 pad = 144B)
#define QSCALE 0.17677669529663687f  // 32^-0.5

__device__ __align__(16) float  g_q [NPIX * CCH];   // [pix][64] fp32 (pre-scaled)
__device__ __align__(16) __half g_kh[NPIX * CCH];   // [pix][64] fp16
__device__ __align__(16) __half g_vh[NPIX * CCH];   // [pix][64] fp16
__device__ __align__(16) float  g_att[CCH * NPIX];  // c-major [c][pix]

// ---------------------------------------------------------------------------
// Kernel 1: qkv = x @ w_qkv + b_qkv. Block tile: 64 px x 96 j (half of 192),
// grid = 512, 96 threads, 8x8 register tile. x and w-half staged in smem.
// ---------------------------------------------------------------------------
__global__ void __launch_bounds__(96) qkv_kernel(const float* __restrict__ vid,
                                                 const float* __restrict__ w_qkv,
                                                 const float* __restrict__ b_qkv) {
    extern __shared__ float sm[];
    float* xs = sm;            // [64][64]  c-major [c][px]
    float* ws = sm + 4096;     // [64][96]  c-major [c][j-local]

    const int tid   = threadIdx.x;
    const int bx    = blockIdx.x;
    const int pix0  = (bx >> 1) * 64;           // one full image row (x fixed)
    const int jbase = (bx & 1) * 96;
    const int n  = pix0 >> 12;
    const int xr = (pix0 >> 6) & 63;
    const float* vbase = vid + n * 262144 + xr * 64;

    for (int i = tid; i < 1024; i += 96) {      // 64 c x 16 quads of x
        const int c = i >> 4, qq = i & 15;
        *(float4*)&xs[c * 64 + qq * 4] = *(const float4*)(vbase + c * 4096 + qq * 4);
    }
#pragma unroll
    for (int it = 0; it < 16; it++) {           // 64 c x 24 quads of w-half
        const int i = tid + it * 96;
        const int c = i / 24, qq = i % 24;
        *(float4*)&ws[c * 96 + qq * 4] = *(const float4*)(w_qkv + c * QKVD + jbase + qq * 4);
    }
    __syncthreads();

    const int pg = tid & 7, jg = tid >> 3;      // 8 px-groups x 12 j-groups
    const int px0 = pg * 8, j0 = jg * 8;

    float acc[8][8];
#pragma unroll
    for (int p = 0; p < 8; p++)
#pragma unroll
        for (int j = 0; j < 8; j++) acc[p][j] = 0.f;

#pragma unroll 4
    for (int c = 0; c < 64; c++) {
        const float4 xa = *(const float4*)&xs[c * 64 + px0];
        const float4 xb = *(const float4*)&xs[c * 64 + px0 + 4];
        const float4 wa = *(const float4*)&ws[c * 96 + j0];
        const float4 wb = *(const float4*)&ws[c * 96 + j0 + 4];
        float xv[8] = {xa.x, xa.y, xa.z, xa.w, xb.x, xb.y, xb.z, xb.w};
        float wv[8] = {wa.x, wa.y, wa.z, wa.w, wb.x, wb.y, wb.z, wb.w};
#pragma unroll
        for (int p = 0; p < 8; p++)
#pragma unroll
            for (int j = 0; j < 8; j++) acc[p][j] += xv[p] * wv[j];
    }

    const int J = jbase + j0;                   // global output column (region-aligned)
    const float4 ba = *(const float4*)(b_qkv + J);
    const float4 bb = *(const float4*)(b_qkv + J + 4);
    const float bv[8] = {ba.x, ba.y, ba.z, ba.w, bb.x, bb.y, bb.z, bb.w};

    if (J < 64) {                               // q: fp32, pre-scaled
#pragma unroll
        for (int p = 0; p < 8; p++) {
            float* dst = g_q + (size_t)(pix0 + px0 + p) * 64 + J;
            float4 r0, r1;
            r0.x = (acc[p][0] + bv[0]) * QSCALE; r0.y = (acc[p][1] + bv[1]) * QSCALE;
            r0.z = (acc[p][2] + bv[2]) * QSCALE; r0.w = (acc[p][3] + bv[3]) * QSCALE;
            r1.x = (acc[p][4] + bv[4]) * QSCALE; r1.y = (acc[p][5] + bv[5]) * QSCALE;
            r1.z = (acc[p][6] + bv[6]) * QSCALE; r1.w = (acc[p][7] + bv[7]) * QSCALE;
            *(float4*)dst = r0; *(float4*)(dst + 4) = r1;
        }
    } else {                                    // k or v: fp16 planar
        __half* base = (J < 128) ? g_kh : g_vh;
        const int off = (J < 128) ? (J - 64) : (J - 128);
#pragma unroll
        for (int p = 0; p < 8; p++) {
            __half2 h0 = __floats2half2_rn(acc[p][0] + bv[0], acc[p][1] + bv[1]);
            __half2 h1 = __floats2half2_rn(acc[p][2] + bv[2], acc[p][3] + bv[3]);
            __half2 h2 = __floats2half2_rn(acc[p][4] + bv[4], acc[p][5] + bv[5]);
            __half2 h3 = __floats2half2_rn(acc[p][6] + bv[6], acc[p][7] + bv[7]);
            uint4 u;
            u.x = *(unsigned int*)&h0; u.y = *(unsigned int*)&h1;
            u.z = *(unsigned int*)&h2; u.w = *(unsigned int*)&h3;
            *(uint4*)(base + (size_t)(pix0 + px0 + p) * 64 + off) = u;
        }
    }
}

// ---------------------------------------------------------------------------
// Kernel 2: neighborhood attention. Block = (8x8 query tile, image), 128
// threads = 64 queries x 2 heads. fp16 k/v 14x14 neighborhood in smem.
// ---------------------------------------------------------------------------
__global__ void __launch_bounds__(128) attn_kernel(const float* __restrict__ rpb) {
    extern __shared__ char smraw[];
    __half* ks = (__half*)smraw;                  // [196][KPITCH]
    __half* vs = ks + NNB * KPITCH;               // [196][KPITCH]
    float*  rs = (float*)(vs + NNB * KPITCH);     // [2][169]

    const int tid  = threadIdx.x;
    const int head = tid >> 6;
    const int qid  = tid & 63;
    const int n    = blockIdx.y;
    const int x0   = (blockIdx.x >> 3) * 8;
    const int y0   = (blockIdx.x & 7) * 8;
    const int rb   = min(max(x0 - 3, 0), 50);
    const int cb   = min(max(y0 - 3, 0), 50);

    const int qx = qid >> 3, qy = qid & 7;
    const int xx = x0 + qx, yy = y0 + qy;
    const int hb = head * DHEAD;
    const int pix = n * 4096 + xx * 64 + yy;

    // q load first: global fetch overlaps staging below
    float q[32];
    {
        const float* qp = g_q + (size_t)pix * 64 + hb;
#pragma unroll
        for (int dq = 0; dq < 8; dq++) {
            const float4 t = *(const float4*)(qp + dq * 4);
            q[dq * 4 + 0] = t.x; q[dq * 4 + 1] = t.y;
            q[dq * 4 + 2] = t.z; q[dq * 4 + 3] = t.w;
        }
    }

    // stage k/v: 196 nb pixels x 16 uint4 (8 k + 8 v), 64 halfs each plane
    for (int i = tid; i < NNB * 16; i += 128) {
        const int nb = i >> 4, part = i & 15;
        const int gr = rb + nb / NBDIM, gc = cb + nb % NBDIM;
        const size_t ps = (size_t)(n * 4096 + gr * 64 + gc) * 64;
        if (part < 8)
            *(uint4*)(ks + nb * KPITCH + part * 8) = *(const uint4*)(g_kh + ps + part * 8);
        else
            *(uint4*)(vs + nb * KPITCH + (part - 8) * 8) = *(const uint4*)(g_vh + ps + (part - 8) * 8);
    }
    for (int i = tid; i < 2 * 169; i += 128) rs[i] = rpb[i];
    __syncthreads();

    const int sx = min(max(xx - 3, 0), 57), sy = min(max(yy - 3, 0), 57);
    const int r0 = sx - rb, c0 = sy - cb;
    const int bh = sx - xx + 6, bw = sy - yy + 6;
    const float* rh = rs + head * 169;

    float lg[49];
#pragma unroll
    for (int a = 0; a < KWIN; a++) {
#pragma unroll
        for (int b = 0; b < KWIN; b++) {
            const __half* kp = ks + ((r0 + a) * NBDIM + c0 + b) * KPITCH + hb;
            float a0 = 0.f, a1 = 0.f, a2 = 0.f, a3 = 0.f;
#pragma unroll
            for (int u = 0; u < 4; u++) {
                const uint4 r = *(const uint4*)(kp + u * 8);
                const float2 f0 = __half22float2(*(const __half2*)&r.x);
                const float2 f1 = __half22float2(*(const __half2*)&r.y);
                const float2 f2 = __half22float2(*(const __half2*)&r.z);
                const float2 f3 = __half22float2(*(const __half2*)&r.w);
                a0 += q[u * 8 + 0] * f0.x + q[u * 8 + 4] * f2.x;
                a1 += q[u * 8 + 1] * f0.y + q[u * 8 + 5] * f2.y;
                a2 += q[u * 8 + 2] * f1.x + q[u * 8 + 6] * f3.x;
                a3 += q[u * 8 + 3] * f1.y + q[u * 8 + 7] * f3.y;
            }
            lg[a * KWIN + b] = (a0 + a1) + (a2 + a3) + rh[(bh + a) * 13 + bw + b];
        }
    }

    float m = lg[0];
#pragma unroll
    for (int i = 1; i < 49; i++) m = fmaxf(m, lg[i]);
    float s = 0.f;
#pragma unroll
    for (int i = 0; i < 49; i++) { const float e = __expf(lg[i] - m); lg[i] = e; s += e; }
    const float inv = 1.0f / s;

    float o[32];
#pragma unroll
    for (int d = 0; d < 32; d++) o[d] = 0.f;
#pragma unroll
    for (int a = 0; a < KWIN; a++) {
#pragma unroll
        for (int b = 0; b < KWIN; b++) {
            const float w = lg[a * KWIN + b];
            const __half* vp = vs + ((r0 + a) * NBDIM + c0 + b) * KPITCH + hb;
#pragma unroll
            for (int u = 0; u < 4; u++) {
                const uint4 r = *(const uint4*)(vp + u * 8);
                const float2 f0 = __half22float2(*(const __half2*)&r.x);
                const float2 f1 = __half22float2(*(const __half2*)&r.y);
                const float2 f2 = __half22float2(*(const __half2*)&r.z);
                const float2 f3 = __half22float2(*(const __half2*)&r.w);
                o[u * 8 + 0] += w * f0.x; o[u * 8 + 1] += w * f0.y;
                o[u * 8 + 2] += w * f1.x; o[u * 8 + 3] += w * f1.y;
                o[u * 8 + 4] += w * f2.x; o[u * 8 + 5] += w * f2.y;
                o[u * 8 + 6] += w * f3.x; o[u * 8 + 7] += w * f3.y;
            }
        }
    }

    // store c-major: g_att[c][pix] (coalesced across qy within the warp)
#pragma unroll
    for (int d = 0; d < 32; d++) g_att[(size_t)(hb + d) * NPIX + pix] = o[d] * inv;
}

// ---------------------------------------------------------------------------
// Kernel 3: out = attn @ w_proj + b_proj. 64 px x 64 cols, 256 threads,
// 4x4 register tile. g_att c-major -> transpose-free float4 smem fill.
// ---------------------------------------------------------------------------
__global__ void __launch_bounds__(256) proj_kernel(const float* __restrict__ w_proj,
                                                   const float* __restrict__ b_proj,
                                                   float* __restrict__ out, int out_size) {
    __shared__ float xs[64][64];   // [c][px]
    const int tid  = threadIdx.x;
    const int pix0 = blockIdx.x * 64;

    for (int i = tid; i < 1024; i += 256) {
        const int c = i >> 4, qq = i & 15;
        *(float4*)&xs[c][qq * 4] = *(const float4*)(g_att + (size_t)c * NPIX + pix0 + qq * 4);
    }
    __syncthreads();

    const int pg = tid >> 4, jg = tid & 15;
    const int px0 = pg * 4, j0 = jg * 4;

    float acc[4][4];
#pragma unroll
    for (int p = 0; p < 4; p++)
#pragma unroll
        for (int j = 0; j < 4; j++) acc[p][j] = 0.f;

#pragma unroll 8
    for (int c = 0; c < 64; c++) {
        const float4 xa = *(const float4*)&xs[c][px0];
        const float4 wa = *(const float4*)(w_proj + c * 64 + j0);
        const float xv[4] = {xa.x, xa.y, xa.z, xa.w};
        const float wv[4] = {wa.x, wa.y, wa.z, wa.w};
#pragma unroll
        for (int p = 0; p < 4; p++)
#pragma unroll
            for (int j = 0; j < 4; j++) acc[p][j] += xv[p] * wv[j];
    }

    const float4 b4 = *(const float4*)(b_proj + j0);
#pragma unroll
    for (int p = 0; p < 4; p++) {
        float4 r;
        r.x = acc[p][0] + b4.x; r.y = acc[p][1] + b4.y;
        r.z = acc[p][2] + b4.z; r.w = acc[p][3] + b4.w;
        *(float4*)(out + (size_t)(pix0 + px0 + p) * 64 + j0) = r;
    }

    if (blockIdx.x == 0) {
        for (int i = NPIX * CCH + tid; i < out_size; i += 256) out[i] = 0.0f;
    }
}

// ---------------------------------------------------------------------------
extern "C" void kernel_launch(void* const* d_in, const int* in_sizes, int n_in,
                              void* d_out, int out_size) {
    const float* vid    = (const float*)d_in[0];
    const float* w_qkv  = (const float*)d_in[4];
    const float* b_qkv  = (const float*)d_in[5];
    const float* rpb    = (const float*)d_in[6];
    const float* w_proj = (const float*)d_in[7];
    const float* b_proj = (const float*)d_in[8];
    float* out = (float*)d_out;

    const int qkv_smem = (64 * 64 + 64 * 96) * (int)sizeof(float);  // 40 KB
    cudaFuncSetAttribute(qkv_kernel, cudaFuncAttributeMaxDynamicSharedMemorySize, qkv_smem);
    qkv_kernel<<<(NPIX / 64) * 2, 96, qkv_smem>>>(vid, w_qkv, b_qkv);

    const int attn_smem = 2 * NNB * KPITCH * (int)sizeof(__half) + 2 * 169 * (int)sizeof(float);
    cudaFuncSetAttribute(attn_kernel, cudaFuncAttributeMaxDynamicSharedMemorySize, attn_smem);
    attn_kernel<<<dim3(64, NIMG), 128, attn_smem>>>(rpb);

    proj_kernel<<<NPIX / 64, 256>>>(w_proj, b_proj, out, out_size);
}

// round 6
// speedup vs baseline: 1.1561x; 1.0323x over previous
#include <cuda_runtime.h>
#include <cuda_fp16.h>

// NATSearch: 2D neighborhood attention (NATTEN-style).
// N=4 images, H=W=64, C=64, HEADS=2, dh=32, K=7.
// qkv GEMM on TENSOR CORES (mma.sync m16n8k16 fp16->fp32) -> dual-head
// neighborhood attention (fp16 k/v smem, fp32 softmax) -> proj GEMM (scalar).

#define NIMG   4
#define HW     64
#define CCH    64
#define NHEADS 2
#define DHEAD  32
#define KWIN   7
#define NPIX   (NIMG * HW * HW)   // 16384
#define QKVD   192
#define NBDIM  14
#define NNB    (NBDIM * NBDIM)    // 196
#define KPITCH 72                 // attn smem pitch in halfs
#define XPITCH 72                 // qkv smem pitch in halfs (144B rows: ldmatrix conflict-free)
#define QSCALE 0.17677669529663687f  // 32^-0.5

__device__ __align__(16) float  g_q [NPIX * CCH];   // [pix][64] fp32 (pre-scaled)
__device__ __align__(16) __half g_kh[NPIX * CCH];   // [pix][64] fp16
__device__ __align__(16) __half g_vh[NPIX * CCH];   // [pix][64] fp16
__device__ __align__(16) float  g_att[CCH * NPIX];  // c-major [c][pix]

// ---------------------------------------------------------------------------
// mma.sync / ldmatrix helpers
// ---------------------------------------------------------------------------
__device__ __forceinline__ void ldsm4(unsigned r[4], unsigned addr) {
    asm volatile("ldmatrix.sync.aligned.m8n8.x4.shared.b16 {%0,%1,%2,%3}, [%4];"
                 : "=r"(r[0]), "=r"(r[1]), "=r"(r[2]), "=r"(r[3]) : "r"(addr));
}
__device__ __forceinline__ void ldsm2(unsigned r[2], unsigned addr) {
    asm volatile("ldmatrix.sync.aligned.m8n8.x2.shared.b16 {%0,%1}, [%2];"
                 : "=r"(r[0]), "=r"(r[1]) : "r"(addr));
}
__device__ __forceinline__ void mma16816(float c[4], const unsigned a[4], const unsigned b[2]) {
    asm volatile(
        "mma.sync.aligned.m16n8k16.row.col.f32.f16.f16.f32 "
        "{%0,%1,%2,%3},{%4,%5,%6,%7},{%8,%9},{%0,%1,%2,%3};"
        : "+f"(c[0]), "+f"(c[1]), "+f"(c[2]), "+f"(c[3])
        : "r"(a[0]), "r"(a[1]), "r"(a[2]), "r"(a[3]), "r"(b[0]), "r"(b[1]));
}

// ---------------------------------------------------------------------------
// Kernel 1: qkv = x @ w_qkv + b_qkv on tensor cores.
// Block: 128 thr / 4 warps, tile 64 px x 192 cols. Warp w: cols [48w, 48w+48).
// A = x[px][c] fp16 (transposed from planar vid), B = w^T[j][c] fp16.
// ---------------------------------------------------------------------------
__global__ void __launch_bounds__(128) qkv_tc_kernel(const float* __restrict__ vid,
                                                     const float* __restrict__ w_qkv,
                                                     const float* __restrict__ b_qkv) {
    __shared__ __half xh[64 * XPITCH];    // [px][c]
    __shared__ __half wh[QKVD * XPITCH];  // [j][c]

    const int tid  = threadIdx.x;
    const int lane = tid & 31;
    const int warp = tid >> 5;
    const int pix0 = blockIdx.x * 64;               // one image row (x fixed)
    const int n  = pix0 >> 12;
    const int xr = (pix0 >> 6) & 63;
    const float* vbase = vid + n * 262144 + xr * 64;

    for (int i = tid; i < 4096; i += 128) {         // x: [c][y] -> xh[y][c]
        const int c = i >> 6, y = i & 63;
        xh[y * XPITCH + c] = __float2half(vbase[c * 4096 + y]);
    }
    for (int i = tid; i < 64 * QKVD; i += 128) {    // w: [c][j] -> wh[j][c]
        const int c = i / QKVD, j = i % QKVD;
        wh[j * XPITCH + c] = __float2half(w_qkv[i]);
    }
    __syncthreads();

    const unsigned xbase = (unsigned)__cvta_generic_to_shared(xh);
    const unsigned wbase = (unsigned)__cvta_generic_to_shared(wh);
    const int wn0 = warp * 48;
    const int arow = lane & 15;                      // ldmatrix x4 row select
    const int acol8 = ((lane >> 4) & 1) * 8;         // +8 col for matrices 2,3
    const int l16 = lane & 15;                       // ldmatrix x2 lanes

#pragma unroll
    for (int nt = 0; nt < 6; nt++) {
        float acc[4][4];
#pragma unroll
        for (int mt = 0; mt < 4; mt++)
#pragma unroll
            for (int r = 0; r < 4; r++) acc[mt][r] = 0.f;

#pragma unroll
        for (int ks = 0; ks < 4; ks++) {
            unsigned bfr[2];
            {
                const int brow = wn0 + nt * 8 + (l16 & 7);
                const int bcol = ks * 16 + ((l16 >> 3) & 1) * 8;
                ldsm2(bfr, wbase + (unsigned)(brow * XPITCH + bcol) * 2u);
            }
#pragma unroll
            for (int mt = 0; mt < 4; mt++) {
                unsigned afr[4];
                const int row = mt * 16 + arow;
                const int col = ks * 16 + acol8;
                ldsm4(afr, xbase + (unsigned)(row * XPITCH + col) * 2u);
                mma16816(acc[mt], afr, bfr);
            }
        }

        // epilogue: thread holds (row lane/4 [+8], cols J,J+1) per m-tile
        const int J = wn0 + nt * 8 + 2 * (lane & 3);
        const float b0 = b_qkv[J], b1 = b_qkv[J + 1];
#pragma unroll
        for (int mt = 0; mt < 4; mt++) {
            const int pxa = pix0 + mt * 16 + (lane >> 2);
            const int pxb = pxa + 8;
            if (J < 64) {
                float2 r0 = make_float2((acc[mt][0] + b0) * QSCALE, (acc[mt][1] + b1) * QSCALE);
                float2 r1 = make_float2((acc[mt][2] + b0) * QSCALE, (acc[mt][3] + b1) * QSCALE);
                *(float2*)(g_q + (size_t)pxa * 64 + J) = r0;
                *(float2*)(g_q + (size_t)pxb * 64 + J) = r1;
            } else if (J < 128) {
                const int off = J - 64;
                *(__half2*)(g_kh + (size_t)pxa * 64 + off) = __floats2half2_rn(acc[mt][0] + b0, acc[mt][1] + b1);
                *(__half2*)(g_kh + (size_t)pxb * 64 + off) = __floats2half2_rn(acc[mt][2] + b0, acc[mt][3] + b1);
            } else {
                const int off = J - 128;
                *(__half2*)(g_vh + (size_t)pxa * 64 + off) = __floats2half2_rn(acc[mt][0] + b0, acc[mt][1] + b1);
                *(__half2*)(g_vh + (size_t)pxb * 64 + off) = __floats2half2_rn(acc[mt][2] + b0, acc[mt][3] + b1);
            }
        }
    }
}

// ---------------------------------------------------------------------------
// Kernel 2: neighborhood attention (unchanged from passing R5).
// ---------------------------------------------------------------------------
__global__ void __launch_bounds__(128) attn_kernel(const float* __restrict__ rpb) {
    extern __shared__ char smraw[];
    __half* ks = (__half*)smraw;                  // [196][KPITCH]
    __half* vs = ks + NNB * KPITCH;               // [196][KPITCH]
    float*  rs = (float*)(vs + NNB * KPITCH);     // [2][169]

    const int tid  = threadIdx.x;
    const int head = tid >> 6;
    const int qid  = tid & 63;
    const int n    = blockIdx.y;
    const int x0   = (blockIdx.x >> 3) * 8;
    const int y0   = (blockIdx.x & 7) * 8;
    const int rb   = min(max(x0 - 3, 0), 50);
    const int cb   = min(max(y0 - 3, 0), 50);

    const int qx = qid >> 3, qy = qid & 7;
    const int xx = x0 + qx, yy = y0 + qy;
    const int hb = head * DHEAD;
    const int pix = n * 4096 + xx * 64 + yy;

    float q[32];
    {
        const float* qp = g_q + (size_t)pix * 64 + hb;
#pragma unroll
        for (int dq = 0; dq < 8; dq++) {
            const float4 t = *(const float4*)(qp + dq * 4);
            q[dq * 4 + 0] = t.x; q[dq * 4 + 1] = t.y;
            q[dq * 4 + 2] = t.z; q[dq * 4 + 3] = t.w;
        }
    }

    for (int i = tid; i < NNB * 16; i += 128) {
        const int nb = i >> 4, part = i & 15;
        const int gr = rb + nb / NBDIM, gc = cb + nb % NBDIM;
        const size_t ps = (size_t)(n * 4096 + gr * 64 + gc) * 64;
        if (part < 8)
            *(uint4*)(ks + nb * KPITCH + part * 8) = *(const uint4*)(g_kh + ps + part * 8);
        else
            *(uint4*)(vs + nb * KPITCH + (part - 8) * 8) = *(const uint4*)(g_vh + ps + (part - 8) * 8);
    }
    for (int i = tid; i < 2 * 169; i += 128) rs[i] = rpb[i];
    __syncthreads();

    const int sx = min(max(xx - 3, 0), 57), sy = min(max(yy - 3, 0), 57);
    const int r0 = sx - rb, c0 = sy - cb;
    const int bh = sx - xx + 6, bw = sy - yy + 6;
    const float* rh = rs + head * 169;

    float lg[49];
#pragma unroll
    for (int a = 0; a < KWIN; a++) {
#pragma unroll
        for (int b = 0; b < KWIN; b++) {
            const __half* kp = ks + ((r0 + a) * NBDIM + c0 + b) * KPITCH + hb;
            float a0 = 0.f, a1 = 0.f, a2 = 0.f, a3 = 0.f;
#pragma unroll
            for (int u = 0; u < 4; u++) {
                const uint4 r = *(const uint4*)(kp + u * 8);
                const float2 f0 = __half22float2(*(const __half2*)&r.x);
                const float2 f1 = __half22float2(*(const __half2*)&r.y);
                const float2 f2 = __half22float2(*(const __half2*)&r.z);
                const float2 f3 = __half22float2(*(const __half2*)&r.w);
                a0 += q[u * 8 + 0] * f0.x + q[u * 8 + 4] * f2.x;
                a1 += q[u * 8 + 1] * f0.y + q[u * 8 + 5] * f2.y;
                a2 += q[u * 8 + 2] * f1.x + q[u * 8 + 6] * f3.x;
                a3 += q[u * 8 + 3] * f1.y + q[u * 8 + 7] * f3.y;
            }
            lg[a * KWIN + b] = (a0 + a1) + (a2 + a3) + rh[(bh + a) * 13 + bw + b];
        }
    }

    float m = lg[0];
#pragma unroll
    for (int i = 1; i < 49; i++) m = fmaxf(m, lg[i]);
    float s = 0.f;
#pragma unroll
    for (int i = 0; i < 49; i++) { const float e = __expf(lg[i] - m); lg[i] = e; s += e; }
    const float inv = 1.0f / s;

    float o[32];
#pragma unroll
    for (int d = 0; d < 32; d++) o[d] = 0.f;
#pragma unroll
    for (int a = 0; a < KWIN; a++) {
#pragma unroll
        for (int b = 0; b < KWIN; b++) {
            const float w = lg[a * KWIN + b];
            const __half* vp = vs + ((r0 + a) * NBDIM + c0 + b) * KPITCH + hb;
#pragma unroll
            for (int u = 0; u < 4; u++) {
                const uint4 r = *(const uint4*)(vp + u * 8);
                const float2 f0 = __half22float2(*(const __half2*)&r.x);
                const float2 f1 = __half22float2(*(const __half2*)&r.y);
                const float2 f2 = __half22float2(*(const __half2*)&r.z);
                const float2 f3 = __half22float2(*(const __half2*)&r.w);
                o[u * 8 + 0] += w * f0.x; o[u * 8 + 1] += w * f0.y;
                o[u * 8 + 2] += w * f1.x; o[u * 8 + 3] += w * f1.y;
                o[u * 8 + 4] += w * f2.x; o[u * 8 + 5] += w * f2.y;
                o[u * 8 + 6] += w * f3.x; o[u * 8 + 7] += w * f3.y;
            }
        }
    }

#pragma unroll
    for (int d = 0; d < 32; d++) g_att[(size_t)(hb + d) * NPIX + pix] = o[d] * inv;
}

// ---------------------------------------------------------------------------
// Kernel 3: out = attn @ w_proj + b_proj (unchanged from passing R5).
// ---------------------------------------------------------------------------
__global__ void __launch_bounds__(256) proj_kernel(const float* __restrict__ w_proj,
                                                   const float* __restrict__ b_proj,
                                                   float* __restrict__ out, int out_size) {
    __shared__ float xs[64][64];
    const int tid  = threadIdx.x;
    const int pix0 = blockIdx.x * 64;

    for (int i = tid; i < 1024; i += 256) {
        const int c = i >> 4, qq = i & 15;
        *(float4*)&xs[c][qq * 4] = *(const float4*)(g_att + (size_t)c * NPIX + pix0 + qq * 4);
    }
    __syncthreads();

    const int pg = tid >> 4, jg = tid & 15;
    const int px0 = pg * 4, j0 = jg * 4;

    float acc[4][4];
#pragma unroll
    for (int p = 0; p < 4; p++)
#pragma unroll
        for (int j = 0; j < 4; j++) acc[p][j] = 0.f;

#pragma unroll 8
    for (int c = 0; c < 64; c++) {
        const float4 xa = *(const float4*)&xs[c][px0];
        const float4 wa = *(const float4*)(w_proj + c * 64 + j0);
        const float xv[4] = {xa.x, xa.y, xa.z, xa.w};
        const float wv[4] = {wa.x, wa.y, wa.z, wa.w};
#pragma unroll
        for (int p = 0; p < 4; p++)
#pragma unroll
            for (int j = 0; j < 4; j++) acc[p][j] += xv[p] * wv[j];
    }

    const float4 b4 = *(const float4*)(b_proj + j0);
#pragma unroll
    for (int p = 0; p < 4; p++) {
        float4 r;
        r.x = acc[p][0] + b4.x; r.y = acc[p][1] + b4.y;
        r.z = acc[p][2] + b4.z; r.w = acc[p][3] + b4.w;
        *(float4*)(out + (size_t)(pix0 + px0 + p) * 64 + j0) = r;
    }

    if (blockIdx.x == 0) {
        for (int i = NPIX * CCH + tid; i < out_size; i += 256) out[i] = 0.0f;
    }
}

// ---------------------------------------------------------------------------
extern "C" void kernel_launch(void* const* d_in, const int* in_sizes, int n_in,
                              void* d_out, int out_size) {
    const float* vid    = (const float*)d_in[0];
    const float* w_qkv  = (const float*)d_in[4];
    const float* b_qkv  = (const float*)d_in[5];
    const float* rpb    = (const float*)d_in[6];
    const float* w_proj = (const float*)d_in[7];
    const float* b_proj = (const float*)d_in[8];
    float* out = (float*)d_out;

    qkv_tc_kernel<<<NPIX / 64, 128>>>(vid, w_qkv, b_qkv);

    const int attn_smem = 2 * NNB * KPITCH * (int)sizeof(__half) + 2 * 169 * (int)sizeof(float);
    cudaFuncSetAttribute(attn_kernel, cudaFuncAttributeMaxDynamicSharedMemorySize, attn_smem);
    attn_kernel<<<dim3(64, NIMG), 128, attn_smem>>>(rpb);

    proj_kernel<<<NPIX / 64, 256>>>(w_proj, b_proj, out, out_size);
}